// round 14
// baseline (speedup 1.0000x reference)
#include <cuda_runtime.h>
#include <stdint.h>

// Problem constants (fixed by the reference)
#define NXD 512
#define NYD 512
#define CH  128
#define QCH 32                          // channels per thread (quarter row)
#define BATCH 4
#define CELLS (NYD * NXD)               // 262144 cells per batch
#define TOTAL_CELLS (BATCH * CELLS)     // 1,048,576  (= 1<<20)

// Per-cell pillar index, stored as p+1 (0 = empty). Self-resetting: gather
// zeroes each cell after consuming it, so the all-zero invariant holds at the
// start of every call (including the first: __device__ arrays are zero-init).
__device__ int g_idx[TOTAL_CELLS];
// Zero feature row for empty cells (zero-initialized, read-only -> hot in L2).
__device__ float4 g_zero_row[CH / 4];

// ---------------------------------------------------------------------------
// Pass 1: scatter pillar index (+1) into canvas. coords row = [b, z, y, x].
// ---------------------------------------------------------------------------
__global__ void build_idx_kernel(const int* __restrict__ coords, int P) {
    int p = blockIdx.x * blockDim.x + threadIdx.x;
    if (p >= P) return;
    int4 c = ((const int4*)coords)[p];               // b, z, y, x
    int cell = (c.x + c.y) * CELLS + c.z * NXD + c.w;
    g_idx[cell] = p + 1;                             // 0 means empty
}

// ---------------------------------------------------------------------------
// Pass 2: gather (R13 roofline structure). CTA = 64 consecutive x-cells x 4
// channel-quarters (256 threads). Warp = 32 consecutive cells of one quarter
// -> every scalar channel store is 128 contiguous bytes per warp instr.
// Each thread reads exactly one 128B feature line (32 channels), 8 float4
// loads front-batched. Output stores are streaming (evict-first).
// After the CTA-wide sync, the cell's index entry is reset to 0 so the next
// graph replay starts from the empty canvas (no memset pass needed).
// ---------------------------------------------------------------------------
__global__ __launch_bounds__(256, 5) void gather_kernel(
    const float* __restrict__ feat, float* __restrict__ out)
{
    __shared__ int s_p[64];

    int t = threadIdx.x;
    int cell0 = blockIdx.x << 6;                     // 64 cells per CTA

    if (t < 64) s_p[t] = g_idx[cell0 + t];
    __syncthreads();
    if (t < 64) g_idx[cell0 + t] = 0;                // reset for next replay

    int q  = t >> 6;                                 // quarter 0..3
    int ci = t & 63;                                 // cell within CTA
    int cell = cell0 + ci;
    int pp = s_p[ci];                                // p+1, 0 = empty

    const float4* r = (pp > 0)
        ? (const float4*)(feat + (size_t)(pp - 1) * CH + q * QCH)
        : (g_zero_row + q * (QCH / 4));

    // Front-batch all 8 loads (one 128B line per thread)
    float4 v0 = __ldg(r + 0);
    float4 v1 = __ldg(r + 1);
    float4 v2 = __ldg(r + 2);
    float4 v3 = __ldg(r + 3);
    float4 v4 = __ldg(r + 4);
    float4 v5 = __ldg(r + 5);
    float4 v6 = __ldg(r + 6);
    float4 v7 = __ldg(r + 7);

    int b = cell >> 18;                              // batch
    float* o = out + (size_t)(b * CH + q * QCH) * CELLS + (cell & (CELLS - 1));

    __stcs(o + (size_t) 0 * CELLS, v0.x);  __stcs(o + (size_t) 1 * CELLS, v0.y);
    __stcs(o + (size_t) 2 * CELLS, v0.z);  __stcs(o + (size_t) 3 * CELLS, v0.w);
    __stcs(o + (size_t) 4 * CELLS, v1.x);  __stcs(o + (size_t) 5 * CELLS, v1.y);
    __stcs(o + (size_t) 6 * CELLS, v1.z);  __stcs(o + (size_t) 7 * CELLS, v1.w);
    __stcs(o + (size_t) 8 * CELLS, v2.x);  __stcs(o + (size_t) 9 * CELLS, v2.y);
    __stcs(o + (size_t)10 * CELLS, v2.z);  __stcs(o + (size_t)11 * CELLS, v2.w);
    __stcs(o + (size_t)12 * CELLS, v3.x);  __stcs(o + (size_t)13 * CELLS, v3.y);
    __stcs(o + (size_t)14 * CELLS, v3.z);  __stcs(o + (size_t)15 * CELLS, v3.w);
    __stcs(o + (size_t)16 * CELLS, v4.x);  __stcs(o + (size_t)17 * CELLS, v4.y);
    __stcs(o + (size_t)18 * CELLS, v4.z);  __stcs(o + (size_t)19 * CELLS, v4.w);
    __stcs(o + (size_t)20 * CELLS, v5.x);  __stcs(o + (size_t)21 * CELLS, v5.y);
    __stcs(o + (size_t)22 * CELLS, v5.z);  __stcs(o + (size_t)23 * CELLS, v5.w);
    __stcs(o + (size_t)24 * CELLS, v6.x);  __stcs(o + (size_t)25 * CELLS, v6.y);
    __stcs(o + (size_t)26 * CELLS, v6.z);  __stcs(o + (size_t)27 * CELLS, v6.w);
    __stcs(o + (size_t)28 * CELLS, v7.x);  __stcs(o + (size_t)29 * CELLS, v7.y);
    __stcs(o + (size_t)30 * CELLS, v7.z);  __stcs(o + (size_t)31 * CELLS, v7.w);
}

// ---------------------------------------------------------------------------
// Launch: identify inputs by size (batch_size scalar / features / coords).
// ---------------------------------------------------------------------------
extern "C" void kernel_launch(void* const* d_in, const int* in_sizes, int n_in,
                              void* d_out, int out_size)
{
    // features is the largest input (P*128 floats); coords has P*4 ints.
    int fi = 0;
    long long best = -1;
    for (int i = 0; i < n_in; ++i) {
        if ((long long)in_sizes[i] > best) { best = in_sizes[i]; fi = i; }
    }
    const float* feat = (const float*)d_in[fi];
    int P = in_sizes[fi] / CH;

    const int* coords = nullptr;
    for (int i = 0; i < n_in; ++i) {
        if (i != fi && in_sizes[i] == P * 4) { coords = (const int*)d_in[i]; break; }
    }
    if (!coords) { // fallback: second-largest input
        int ci = -1; long long b2 = -1;
        for (int i = 0; i < n_in; ++i)
            if (i != fi && (long long)in_sizes[i] > b2) { b2 = in_sizes[i]; ci = i; }
        coords = (const int*)d_in[ci];
    }

    float* out = (float*)d_out;

    // Pass 1: scatter pillar indices (canvas is all-zero by invariant)
    build_idx_kernel<<<(P + 255) / 256, 256>>>(coords, P);

    // Pass 2: gather + transpose + canvas self-reset (64 cells x 4 quarters/CTA)
    gather_kernel<<<TOTAL_CELLS / 64, 256>>>(feat, out);
}

// round 16
// speedup vs baseline: 1.0484x; 1.0484x over previous
#include <cuda_runtime.h>
#include <stdint.h>

// Problem constants (fixed by the reference)
#define NXD 512
#define NYD 512
#define CH  128
#define QCH 32                          // channels per thread (quarter row)
#define BATCH 4
#define CELLS (NYD * NXD)               // 262144 cells per batch
#define TOTAL_CELLS (BATCH * CELLS)     // 1,048,576  (= 1<<20)

// Scratch: per-cell pillar index, reset to -1 each call via a 0xFF memset node.
__device__ int g_idx[TOTAL_CELLS];
// Zero feature row for empty cells (zero-initialized, read-only -> hot in L2).
__device__ float4 g_zero_row[CH / 4];

// ---------------------------------------------------------------------------
// Pass 1: scatter pillar index into canvas. coords row = [b, z, y, x], NZ=1.
// FOUR pillars per thread, front-batched int4 loads (MLP=4) to cut the
// latency-bound duration of this small kernel.
// ---------------------------------------------------------------------------
__global__ void build_idx_kernel(const int4* __restrict__ coords4, int P) {
    int t = blockIdx.x * blockDim.x + threadIdx.x;
    int p0 = t * 4;
    if (p0 + 3 < P) {
        int4 c0 = __ldg(coords4 + p0 + 0);
        int4 c1 = __ldg(coords4 + p0 + 1);
        int4 c2 = __ldg(coords4 + p0 + 2);
        int4 c3 = __ldg(coords4 + p0 + 3);
        __stcs(&g_idx[(c0.x + c0.y) * CELLS + c0.z * NXD + c0.w], p0 + 0);
        __stcs(&g_idx[(c1.x + c1.y) * CELLS + c1.z * NXD + c1.w], p0 + 1);
        __stcs(&g_idx[(c2.x + c2.y) * CELLS + c2.z * NXD + c2.w], p0 + 2);
        __stcs(&g_idx[(c3.x + c3.y) * CELLS + c3.z * NXD + c3.w], p0 + 3);
    } else {
        for (int p = p0; p < P; ++p) {
            int4 c = __ldg(coords4 + p);
            __stcs(&g_idx[(c.x + c.y) * CELLS + c.z * NXD + c.w], p);
        }
    }
}

// ---------------------------------------------------------------------------
// Pass 2: gather — EXACT R13 structure (best measured: 117.95us, DRAM 68%).
// FOUR threads per cell, each owning 32 channels (one 128B feature line).
// Quarter selected by high grid bits -> consecutive threads = consecutive x
// cells -> each warp scalar-store instr covers 128 contiguous bytes.
// All 8 float4 loads front-batched (MLP=8); streaming stores.
// ---------------------------------------------------------------------------
__global__ __launch_bounds__(256, 5) void gather_kernel(
    const float* __restrict__ feat, float* __restrict__ out)
{
    int t = blockIdx.x * blockDim.x + threadIdx.x;   // 4*TOTAL_CELLS threads
    int q    = t >> 20;                              // quarter: ch [32q, 32q+32)
    int cell = t & (TOTAL_CELLS - 1);

    int p = __ldg(g_idx + cell);                     // coalesced 128B/warp

    const float4* r = (p >= 0)
        ? (const float4*)(feat + (size_t)p * CH + q * QCH)
        : (g_zero_row + q * (QCH / 4));

    // Front-batch all 8 loads (one 128B line per thread)
    float4 v0 = __ldg(r + 0);
    float4 v1 = __ldg(r + 1);
    float4 v2 = __ldg(r + 2);
    float4 v3 = __ldg(r + 3);
    float4 v4 = __ldg(r + 4);
    float4 v5 = __ldg(r + 5);
    float4 v6 = __ldg(r + 6);
    float4 v7 = __ldg(r + 7);

    int b = cell >> 18;                              // batch
    float* o = out + (size_t)(b * CH + q * QCH) * CELLS + (cell & (CELLS - 1));

    __stcs(o + (size_t) 0 * CELLS, v0.x);  __stcs(o + (size_t) 1 * CELLS, v0.y);
    __stcs(o + (size_t) 2 * CELLS, v0.z);  __stcs(o + (size_t) 3 * CELLS, v0.w);
    __stcs(o + (size_t) 4 * CELLS, v1.x);  __stcs(o + (size_t) 5 * CELLS, v1.y);
    __stcs(o + (size_t) 6 * CELLS, v1.z);  __stcs(o + (size_t) 7 * CELLS, v1.w);
    __stcs(o + (size_t) 8 * CELLS, v2.x);  __stcs(o + (size_t) 9 * CELLS, v2.y);
    __stcs(o + (size_t)10 * CELLS, v2.z);  __stcs(o + (size_t)11 * CELLS, v2.w);
    __stcs(o + (size_t)12 * CELLS, v3.x);  __stcs(o + (size_t)13 * CELLS, v3.y);
    __stcs(o + (size_t)14 * CELLS, v3.z);  __stcs(o + (size_t)15 * CELLS, v3.w);
    __stcs(o + (size_t)16 * CELLS, v4.x);  __stcs(o + (size_t)17 * CELLS, v4.y);
    __stcs(o + (size_t)18 * CELLS, v4.z);  __stcs(o + (size_t)19 * CELLS, v4.w);
    __stcs(o + (size_t)20 * CELLS, v5.x);  __stcs(o + (size_t)21 * CELLS, v5.y);
    __stcs(o + (size_t)22 * CELLS, v5.z);  __stcs(o + (size_t)23 * CELLS, v5.w);
    __stcs(o + (size_t)24 * CELLS, v6.x);  __stcs(o + (size_t)25 * CELLS, v6.y);
    __stcs(o + (size_t)26 * CELLS, v6.z);  __stcs(o + (size_t)27 * CELLS, v6.w);
    __stcs(o + (size_t)28 * CELLS, v7.x);  __stcs(o + (size_t)29 * CELLS, v7.y);
    __stcs(o + (size_t)30 * CELLS, v7.z);  __stcs(o + (size_t)31 * CELLS, v7.w);
}

// ---------------------------------------------------------------------------
// Launch: identify inputs by size (batch_size scalar / features / coords).
// ---------------------------------------------------------------------------
extern "C" void kernel_launch(void* const* d_in, const int* in_sizes, int n_in,
                              void* d_out, int out_size)
{
    // features is the largest input (P*128 floats); coords has P*4 ints.
    int fi = 0;
    long long best = -1;
    for (int i = 0; i < n_in; ++i) {
        if ((long long)in_sizes[i] > best) { best = in_sizes[i]; fi = i; }
    }
    const float* feat = (const float*)d_in[fi];
    int P = in_sizes[fi] / CH;

    const int* coords = nullptr;
    for (int i = 0; i < n_in; ++i) {
        if (i != fi && in_sizes[i] == P * 4) { coords = (const int*)d_in[i]; break; }
    }
    if (!coords) { // fallback: second-largest input
        int ci = -1; long long b2 = -1;
        for (int i = 0; i < n_in; ++i)
            if (i != fi && (long long)in_sizes[i] > b2) { b2 = in_sizes[i]; ci = i; }
        coords = (const int*)d_in[ci];
    }

    float* out = (float*)d_out;

    // Pass 0: reset index canvas to -1 (0xFF bytes). Memset node: capturable.
    void* idx_ptr = nullptr;
    cudaGetSymbolAddress(&idx_ptr, g_idx);
    cudaMemsetAsync(idx_ptr, 0xFF, TOTAL_CELLS * sizeof(int), 0);

    // Pass 1: scatter pillar indices (4 pillars per thread, MLP=4)
    int nthreads = (P + 3) / 4;
    build_idx_kernel<<<(nthreads + 255) / 256, 256>>>((const int4*)coords, P);

    // Pass 2: gather + transpose (4 threads per cell, 32 channels each)
    gather_kernel<<<(4 * TOTAL_CELLS) / 256, 256>>>(feat, out);
}